// round 14
// baseline (speedup 1.0000x reference)
#include <cuda_runtime.h>
#include <math.h>

#define Nn   8000
#define NPc  1000
#define Bc   8
#define Fc   1000
#define HCc  32
#define TRIc 499500
#define HIDc 128
#define EPSc 1e-5f
#define HPLANE (Bc * NPc * HCc)

typedef unsigned long long u64;

// ---------------- persistent scratch ----------------
__device__ int    g_bar[32];
__device__ int    g_cursor;                  // gemm chunk cursor (memset per launch)
__device__ float  g_hbuf[2 * HPLANE];        // h planes (layers 0,1)
__device__ float  g_hv[64 * 20000];          // per-block v-tables: [blk][k][d] float4
__device__ float  g_emb[Bc * 96];
__device__ float  g_y1[Bc * HIDc];

// monotonic N-block barrier (replay-safe, never reset)
__device__ __forceinline__ void gbarN(int slot, int nb) {
    __syncthreads();
    if (threadIdx.x == 0) {
        __threadfence();
        int r = atomicAdd(&g_bar[slot], 1);
        int target = (r / nb + 1) * nb;
        while (atomicAdd(&g_bar[slot], 0) < target) { }
    }
    __syncthreads();
}

// ---------------- f32x2 packed helpers ----------------
__device__ __forceinline__ u64 pk2(float a, float b) {
    u64 r;
    asm("mov.b64 %0, {%1, %2};" : "=l"(r) : "r"(__float_as_uint(a)), "r"(__float_as_uint(b)));
    return r;
}
__device__ __forceinline__ u64 ffma2(u64 a, u64 b, u64 c) {
    u64 d;
    asm("fma.rn.f32x2 %0, %1, %2, %3;" : "=l"(d) : "l"(a), "l"(b), "l"(c));
    return d;
}
__device__ __forceinline__ float2 upk(u64 a) {
    unsigned lo, hi;
    asm("mov.b64 {%0, %1}, %2;" : "=r"(lo), "=r"(hi) : "l"(a));
    return make_float2(__uint_as_float(lo), __uint_as_float(hi));
}

// fast tanh: exp-based, no overflow, rel err ~1e-6
__device__ __forceinline__ float ftanh(float x) {
    float ax = fabsf(x);
    float e = __expf(-2.f * ax);
    float r = __fdividef(1.f - e, 1.f + e);
    return copysignf(r, x);
}

// ---------------- cheb smem layout (floats) ----------------
#define SM_A    0          // 4000 (float4[1000])   | aliased: pDeg/pCnt/pCur
#define SM_B    4000       // 4000                  | aliased: pScan(32)
#define SM_EM   8000       // 20000 (float2 per edge: {w, idx-bits})
#define SM_ROW  28000      // 1008
#define SM_W    29008      // 640 (5x32x4)
#define SM_POOL 29648      // 128 (32 warps x 4)
#define SM_TOT  29776      // 119104 bytes

// ---------------- float4 smem gather: f32x2 math, 2-deep LDS ----------------
__device__ __forceinline__ float4 gat4(const float4* __restrict__ S,
                                       const float2* __restrict__ sEm,
                                       const int* __restrict__ sRow, int d) {
    int i0 = sRow[d], i1 = sRow[d + 1];
    u64 a0 = 0ull, a1 = 0ull;
    int i = i0;
    for (; i + 2 <= i1; i += 2) {
        float2 m0 = sEm[i], m1 = sEm[i + 1];
        ulonglong2 s0 = *(const ulonglong2*)&S[__float_as_int(m0.y)];
        ulonglong2 s1 = *(const ulonglong2*)&S[__float_as_int(m1.y)];
        u64 w0 = pk2(m0.x, m0.x), w1 = pk2(m1.x, m1.x);
        a0 = ffma2(w0, s0.x, a0); a1 = ffma2(w0, s0.y, a1);
        a0 = ffma2(w1, s1.x, a0); a1 = ffma2(w1, s1.y, a1);
    }
    if (i < i1) {
        float2 m0 = sEm[i];
        ulonglong2 s0 = *(const ulonglong2*)&S[__float_as_int(m0.y)];
        u64 w0 = pk2(m0.x, m0.x);
        a0 = ffma2(w0, s0.x, a0); a1 = ffma2(w0, s0.y, a1);
    }
    float2 f0 = upk(a0), f1 = upk(a1);
    return make_float4(f0.x, f0.y, f1.x, f1.y);
}

// ---------------- one ChebConv layer: node-per-thread, 4 channels ----------------
// mode 0: v_k[d] = cw0[k][d][ch0..ch0+4)   (layer-0 identity input)
// mode 1: v_k[d] = vt4[k*1000 + d]
__device__ void run_layer(int L, int mode, int b, int ch0, int t,
                          float4* sA4, float4* sB4,
                          const int* sRow, const float2* sEm,
                          const float* __restrict__ vsrc, const float4* __restrict__ vt4,
                          const float* __restrict__ cbL, float* sPool)
{
#define VR(k, d) (mode == 0 ? __ldg((const float4*)(vsrc + (k) * 32000 + (d) * 32 + ch0)) \
                            : __ldcg(vt4 + (k) * 1000 + (d)))
    int d = t;
    bool act = (d < NPc);
    if (act) sA4[d] = VR(4, d);
    __syncthreads();
    if (act) {
        float4 g = gat4(sA4, sEm, sRow, d);
        float4 v = VR(3, d);
        sB4[d] = make_float4(fmaf(2.f, g.x, v.x), fmaf(2.f, g.y, v.y),
                             fmaf(2.f, g.z, v.z), fmaf(2.f, g.w, v.w));
    }
    __syncthreads();
    if (act) {
        float4 g = gat4(sB4, sEm, sRow, d);
        float4 v = VR(2, d);
        float4 o = sA4[d];
        sA4[d] = make_float4(fmaf(2.f, g.x, v.x) - o.x, fmaf(2.f, g.y, v.y) - o.y,
                             fmaf(2.f, g.z, v.z) - o.z, fmaf(2.f, g.w, v.w) - o.w);
    }
    __syncthreads();
    if (act) {
        float4 g = gat4(sA4, sEm, sRow, d);
        float4 v = VR(1, d);
        float4 o = sB4[d];
        sB4[d] = make_float4(fmaf(2.f, g.x, v.x) - o.x, fmaf(2.f, g.y, v.y) - o.y,
                             fmaf(2.f, g.z, v.z) - o.z, fmaf(2.f, g.w, v.w) - o.w);
    }
    __syncthreads();
    // final: h = tanh(v0 + G(B) - A + bias)
    float4 pool = make_float4(0.f, 0.f, 0.f, 0.f);
    if (act) {
        float4 g = gat4(sB4, sEm, sRow, d);
        float4 v = VR(0, d);
        float4 o = sA4[d];
        float4 bias4 = __ldg((const float4*)(cbL + ch0));
        float4 h;
        h.x = ftanh(v.x + g.x - o.x + bias4.x);
        h.y = ftanh(v.y + g.y - o.y + bias4.y);
        h.z = ftanh(v.z + g.z - o.z + bias4.z);
        h.w = ftanh(v.w + g.w - o.w + bias4.w);
        pool = h;
        if (L < 2)
            *(float4*)(g_hbuf + L * HPLANE + b * NPc * HCc + d * HCc + ch0) = h;
    }
    // pool reduce: warp shuffles, per-warp smem, direct store (block owns its cols)
#pragma unroll
    for (int off = 16; off >= 1; off >>= 1) {
        pool.x += __shfl_down_sync(0xFFFFFFFFu, pool.x, off);
        pool.y += __shfl_down_sync(0xFFFFFFFFu, pool.y, off);
        pool.z += __shfl_down_sync(0xFFFFFFFFu, pool.z, off);
        pool.w += __shfl_down_sync(0xFFFFFFFFu, pool.w, off);
    }
    int wid = t >> 5, lid = t & 31;
    if (lid == 0) *(float4*)(sPool + wid * 4) = pool;
    __syncthreads();
    if (t < 4) {
        float s = 0.f;
#pragma unroll
        for (int w = 0; w < 32; w++) s += sPool[w * 4 + t];
        g_emb[b * 96 + L * 32 + ch0 + t] = s;
    }
    __syncthreads();
#undef VR
}

// ---------------- v-table pass: vt4[k*1000+d] = h[d][:] @ W[k][:, ch0..ch0+4) ----------------
__device__ void vpass(const float* __restrict__ hprev,   // batch base [d][32]
                      const float* __restrict__ cwL,     // (5,32,32)
                      float4* __restrict__ vt4, float* sW, int ch0, int t)
{
    for (int idx = t; idx < 640; idx += 1024) {
        int c = idx & 3, j = (idx >> 2) & 31, k = idx >> 7;
        sW[idx] = __ldg(cwL + k * 1024 + j * 32 + ch0 + c);
    }
    __syncthreads();
    int d = t;
    if (d < NPc) {
        float4 hv[8];
#pragma unroll
        for (int q = 0; q < 8; q++)
            hv[q] = __ldcg((const float4*)(hprev + d * 32 + q * 4));
        const float* hh = (const float*)hv;
#pragma unroll
        for (int k = 0; k < 5; k++) {
            u64 a0 = 0ull, a1 = 0ull;
#pragma unroll
            for (int j = 0; j < 32; j++) {
                u64 hj2 = pk2(hh[j], hh[j]);
                ulonglong2 wr = *(const ulonglong2*)&sW[k * 128 + j * 4];
                a0 = ffma2(hj2, wr.x, a0);
                a1 = ffma2(hj2, wr.y, a1);
            }
            float2 f0 = upk(a0), f1 = upk(a1);
            vt4[k * 1000 + d] = make_float4(f0.x, f0.y, f1.x, f1.y);
        }
    }
    __syncthreads();
}

// ---------------- the cheb kernel: 64 blocks x 1024 threads ----------------
__global__ void __launch_bounds__(1024, 1)
cheb_kernel(const int* __restrict__ src, const int* __restrict__ dst, int E,
            const float* __restrict__ cw0, const float* __restrict__ cb0,
            const float* __restrict__ cw1, const float* __restrict__ cb1,
            const float* __restrict__ cw2, const float* __restrict__ cb2)
{
    extern __shared__ float sm[];
    float4* sA4 = (float4*)(sm + SM_A);
    float4* sB4 = (float4*)(sm + SM_B);
    float2* sEm = (float2*)(sm + SM_EM);
    int* sRow   = (int*)(sm + SM_ROW);
    float* sW   = sm + SM_W;
    float* sPool= sm + SM_POOL;
    // CSR-build scratch aliased over sA/sB (dead until first pass)
    int* pDeg  = (int*)(sm + SM_A);
    int* pCnt  = (int*)(sm + SM_A) + 1000;
    int* pCur  = (int*)(sm + SM_A) + 2000;
    int* pScan = (int*)(sm + SM_B);    // 32 warp totals

    const int t = threadIdx.x, blk = blockIdx.x;
    const int b = blk >> 3, r = blk & 7;
    const int ch0 = r * 4;
    const int EB = E / Bc;
    const int e0 = b * EB;
    const int lane = t & 31, wid = t >> 5;
    float4* vt4 = (float4*)(g_hv + blk * 20000);

    // ---- in-block CSR build for batch b ----
    if (t < NPc) { pDeg[t] = 0; pCnt[t] = 0; }
    __syncthreads();
    for (int e = e0 + t; e < e0 + EB; e += 1024) {
        atomicAdd(&pDeg[__ldg(src + e) - b * NPc], 1);
        atomicAdd(&pCnt[__ldg(dst + e) - b * NPc], 1);
    }
    __syncthreads();
    {   // warp-shuffle exclusive scan of pCnt (1024 elements, 2 barriers)
        int c = (t < NPc) ? pCnt[t] : 0;
        int v = c;
#pragma unroll
        for (int off = 1; off < 32; off <<= 1) {
            int n = __shfl_up_sync(0xFFFFFFFFu, v, off);
            if (lane >= off) v += n;
        }
        if (lane == 31) pScan[wid] = v;          // warp total
        __syncthreads();
        if (wid == 0) {
            int w = pScan[lane];
#pragma unroll
            for (int off = 1; off < 32; off <<= 1) {
                int n = __shfl_up_sync(0xFFFFFFFFu, w, off);
                if (lane >= off) w += n;
            }
            pScan[lane] = w;                     // inclusive totals
        }
        __syncthreads();
        int incl = v + (wid > 0 ? pScan[wid - 1] : 0);
        int excl = incl - c;
        if (t < NPc) { sRow[t] = excl; pCur[t] = excl; }
        if (t == 1023) sRow[NPc] = incl;         // grand total
    }
    __syncthreads();
    for (int e = e0 + t; e < e0 + EB; e += 1024) {
        int s_ = __ldg(src + e) - b * NPc;
        int d_ = __ldg(dst + e) - b * NPc;
        int ds = pDeg[s_], dd = pDeg[d_];
        float w = (ds > 0 && dd > 0) ? -rsqrtf((float)ds) * rsqrtf((float)dd) : 0.f;
        int pos = atomicAdd(&pCur[d_], 1);
        sEm[pos] = make_float2(w, __int_as_float(s_));
    }
    __syncthreads();   // scratch dead; sA/sB reusable

    // ---- layer 0 (v-tables = cw0 planes) ----
    run_layer(0, 0, b, ch0, t, sA4, sB4, sRow, sEm, cw0, nullptr, cb0, sPool);

    __threadfence();
    gbarN(b * 2 + 0, 8);
    vpass(g_hbuf + 0 * HPLANE + b * NPc * HCc, cw1, vt4, sW, ch0, t);
    run_layer(1, 1, b, ch0, t, sA4, sB4, sRow, sEm, nullptr, vt4, cb1, sPool);

    __threadfence();
    gbarN(b * 2 + 1, 8);
    vpass(g_hbuf + 1 * HPLANE + b * NPc * HCc, cw2, vt4, sW, ch0, t);
    run_layer(2, 1, b, ch0, t, sA4, sB4, sRow, sEm, nullptr, vt4, cb2, sPool);
}

// ---------------- GEMM kernel: dynamic chunks, 8-deep prefetch ----------------
#define GNB   296
#define GCH   256
#define GNCH  ((TRIc + GCH - 1) / GCH)   // 1952

__device__ __forceinline__ void triidx(int f, int& i, int& j) {
    float disc = 3996001.0f - 8.0f * (float)f;
    float sq = sqrtf(fmaxf(disc, 0.f));
    i = (int)((1999.0f - sq) * 0.5f);
    i = max(0, min(i, Fc - 2));
    while (i + 1 <= Fc - 2 && (((long long)(i + 1) * (1999 - (i + 1))) >> 1) <= (long long)f) i++;
    while (i > 0 && (((long long)i * (1999 - i)) >> 1) > (long long)f) i--;
    int Si = (int)(((long long)i * (1999 - i)) >> 1);
    j = i + 1 + (f - Si);
}

__global__ void __launch_bounds__(256, 2)
gemm_kernel(const float* __restrict__ x, const float* __restrict__ W1,
            const float* __restrict__ bng, const float* __restrict__ bnb)
{
    __shared__ float sfb[2][GCH * 8];
    __shared__ float sred[4096];
    __shared__ int sChunk;
    int t = threadIdx.x, wp = t >> 5, l = t & 31;
    float acc[Bc][4];
#pragma unroll
    for (int b = 0; b < Bc; b++)
#pragma unroll
        for (int q = 0; q < 4; q++) acc[b][q] = 0.f;

    if (t == 0) sChunk = atomicAdd(&g_cursor, 1);
    __syncthreads();
    int c = sChunk;
    __syncthreads();
    if (c < GNCH) {
        int f = c * GCH + t;
        float res[Bc];
        if (f < TRIc) {
            int i, j; triidx(f, i, j);
            float v[Bc]; float m = 0.f;
#pragma unroll
            for (int b = 0; b < Bc; b++) { v[b] = __ldg(x + ((size_t)(b * Fc + i) * Fc + j)); m += v[b]; }
            m *= 0.125f;
            float var = 0.f;
#pragma unroll
            for (int b = 0; b < Bc; b++) { float dd = v[b] - m; var = fmaf(dd, dd, var); }
            var *= 0.125f;
            float sc = rsqrtf(var + EPSc) * __ldg(bng + f);
            float sh = __ldg(bnb + f);
#pragma unroll
            for (int b = 0; b < Bc; b++) res[b] = (v[b] - m) * sc + sh;
        } else {
#pragma unroll
            for (int b = 0; b < Bc; b++) res[b] = 0.f;
        }
        *(float4*)&sfb[0][t * 8]     = make_float4(res[0], res[1], res[2], res[3]);
        *(float4*)&sfb[0][t * 8 + 4] = make_float4(res[4], res[5], res[6], res[7]);
    }
    __syncthreads();

    int p = 0;
    while (c < GNCH) {
        if (t == 0) sChunk = atomicAdd(&g_cursor, 1);
        __syncthreads();
        int cn = sChunk;
        __syncthreads();
        bool hasN = (cn < GNCH);
        float xv[Bc]; float bgv = 0.f, bbv = 0.f; bool val = false;
        if (hasN) {
            int fN = cn * GCH + t;
            val = (fN < TRIc);
            if (val) {
                int i, j; triidx(fN, i, j);
#pragma unroll
                for (int b = 0; b < Bc; b++)
                    xv[b] = __ldg(x + ((size_t)(b * Fc + i) * Fc + j));
                bgv = __ldg(bng + fN);
                bbv = __ldg(bnb + fN);
            }
        }
        {
            int fbase = c * GCH;
            int r0 = wp * 32;
            const float* buf = sfb[p];
            for (int rb = 0; rb < 32; rb += 8) {
                float4 w[8];
#pragma unroll
                for (int u = 0; u < 8; u++) {
                    int f2 = min(fbase + r0 + rb + u, TRIc - 1);
                    w[u] = __ldcs((const float4*)(W1 + (size_t)f2 * HIDc + l * 4));
                }
#pragma unroll
                for (int u = 0; u < 8; u++) {
                    int fl = r0 + rb + u;
                    float4 f0 = *(const float4*)&buf[fl * 8];
                    float4 f1 = *(const float4*)&buf[fl * 8 + 4];
                    acc[0][0] = fmaf(f0.x, w[u].x, acc[0][0]); acc[0][1] = fmaf(f0.x, w[u].y, acc[0][1]);
                    acc[0][2] = fmaf(f0.x, w[u].z, acc[0][2]); acc[0][3] = fmaf(f0.x, w[u].w, acc[0][3]);
                    acc[1][0] = fmaf(f0.y, w[u].x, acc[1][0]); acc[1][1] = fmaf(f0.y, w[u].y, acc[1][1]);
                    acc[1][2] = fmaf(f0.y, w[u].z, acc[1][2]); acc[1][3] = fmaf(f0.y, w[u].w, acc[1][3]);
                    acc[2][0] = fmaf(f0.z, w[u].x, acc[2][0]); acc[2][1] = fmaf(f0.z, w[u].y, acc[2][1]);
                    acc[2][2] = fmaf(f0.z, w[u].z, acc[2][2]); acc[2][3] = fmaf(f0.z, w[u].w, acc[2][3]);
                    acc[3][0] = fmaf(f0.w, w[u].x, acc[3][0]); acc[3][1] = fmaf(f0.w, w[u].y, acc[3][1]);
                    acc[3][2] = fmaf(f0.w, w[u].z, acc[3][2]); acc[3][3] = fmaf(f0.w, w[u].w, acc[3][3]);
                    acc[4][0] = fmaf(f1.x, w[u].x, acc[4][0]); acc[4][1] = fmaf(f1.x, w[u].y, acc[4][1]);
                    acc[4][2] = fmaf(f1.x, w[u].z, acc[4][2]); acc[4][3] = fmaf(f1.x, w[u].w, acc[4][3]);
                    acc[5][0] = fmaf(f1.y, w[u].x, acc[5][0]); acc[5][1] = fmaf(f1.y, w[u].y, acc[5][1]);
                    acc[5][2] = fmaf(f1.y, w[u].z, acc[5][2]); acc[5][3] = fmaf(f1.y, w[u].w, acc[5][3]);
                    acc[6][0] = fmaf(f1.z, w[u].x, acc[6][0]); acc[6][1] = fmaf(f1.z, w[u].y, acc[6][1]);
                    acc[6][2] = fmaf(f1.z, w[u].z, acc[6][2]); acc[6][3] = fmaf(f1.z, w[u].w, acc[6][3]);
                    acc[7][0] = fmaf(f1.w, w[u].x, acc[7][0]); acc[7][1] = fmaf(f1.w, w[u].y, acc[7][1]);
                    acc[7][2] = fmaf(f1.w, w[u].z, acc[7][2]); acc[7][3] = fmaf(f1.w, w[u].w, acc[7][3]);
                }
            }
        }
        if (hasN) {
            float res[Bc];
            if (val) {
                float m = 0.f;
#pragma unroll
                for (int b = 0; b < Bc; b++) m += xv[b];
                m *= 0.125f;
                float var = 0.f;
#pragma unroll
                for (int b = 0; b < Bc; b++) { float dd = xv[b] - m; var = fmaf(dd, dd, var); }
                var *= 0.125f;
                float sc = rsqrtf(var + EPSc) * bgv;
#pragma unroll
                for (int b = 0; b < Bc; b++) res[b] = (xv[b] - m) * sc + bbv;
            } else {
#pragma unroll
                for (int b = 0; b < Bc; b++) res[b] = 0.f;
            }
            *(float4*)&sfb[p ^ 1][t * 8]     = make_float4(res[0], res[1], res[2], res[3]);
            *(float4*)&sfb[p ^ 1][t * 8 + 4] = make_float4(res[4], res[5], res[6], res[7]);
        }
        __syncthreads();
        c = cn;
        p ^= 1;
    }

    for (int half = 4; half >= 1; half >>= 1) {
        if (wp >= half && wp < 2 * half) {
            float* reg = sred + (wp - half) * 1024;
#pragma unroll
            for (int b = 0; b < Bc; b++)
                *(float4*)&reg[b * HIDc + l * 4] =
                    make_float4(acc[b][0], acc[b][1], acc[b][2], acc[b][3]);
        }
        __syncthreads();
        if (wp < half) {
            float* reg = sred + wp * 1024;
#pragma unroll
            for (int b = 0; b < Bc; b++) {
                float4 z = *(const float4*)&reg[b * HIDc + l * 4];
                acc[b][0] += z.x; acc[b][1] += z.y; acc[b][2] += z.z; acc[b][3] += z.w;
            }
        }
        __syncthreads();
    }
    if (wp == 0) {
#pragma unroll
        for (int b = 0; b < Bc; b++)
#pragma unroll
            for (int q = 0; q < 4; q++)
                atomicAdd(&g_y1[b * HIDc + l * 4 + q], acc[b][q]);
    }
}

// ---------------- head ----------------
__global__ void head_kernel(const float* __restrict__ bnhg, const float* __restrict__ bnhb,
                            const float* __restrict__ b1,
                            const float* __restrict__ g1, const float* __restrict__ be1,
                            const float* __restrict__ W2, const float* __restrict__ b2,
                            const float* __restrict__ g2, const float* __restrict__ be2,
                            const float* __restrict__ W3, const float* __restrict__ b3,
                            const float* __restrict__ g3, const float* __restrict__ be3,
                            const float* __restrict__ W4, const float* __restrict__ b4,
                            float* __restrict__ out) {
    __shared__ float a1[8 * 128];
    __shared__ float a2[8 * 64];
    __shared__ float a3[8 * 64];
    __shared__ float lg[16];
    int t = threadIdx.x;

    if (t < 96) {
        float e[Bc]; float m = 0.f;
#pragma unroll
        for (int b = 0; b < Bc; b++) { e[b] = __ldcg(&g_emb[b * 96 + t]) * (1.f / (float)NPc); m += e[b]; }
        m *= 0.125f;
        float v = 0.f;
#pragma unroll
        for (int b = 0; b < Bc; b++) { float dd = e[b] - m; v = fmaf(dd, dd, v); }
        v *= 0.125f;
        float sc = rsqrtf(v + EPSc) * __ldg(bnhg + t);
        float sh = __ldg(bnhb + t);
#pragma unroll
        for (int b = 0; b < Bc; b++) out[16 + b * 96 + t] = (e[b] - m) * sc + sh;
    }

    for (int idx = t; idx < 1024; idx += 256) a1[idx] = __ldcg(&g_y1[idx]) + __ldg(&b1[idx & 127]);
    __syncthreads();
    if (t < 128) {
        float m = 0.f;
#pragma unroll
        for (int b = 0; b < Bc; b++) m += a1[b * 128 + t];
        m *= 0.125f;
        float v = 0.f;
#pragma unroll
        for (int b = 0; b < Bc; b++) { float dd = a1[b * 128 + t] - m; v = fmaf(dd, dd, v); }
        v *= 0.125f;
        float sc = rsqrtf(v + EPSc) * __ldg(g1 + t);
        float sh = __ldg(be1 + t);
#pragma unroll
        for (int b = 0; b < Bc; b++) {
            float z = (a1[b * 128 + t] - m) * sc + sh;
            a1[b * 128 + t] = z > 0.f ? z : 0.f;
        }
    }
    __syncthreads();
    for (int idx = t; idx < 512; idx += 256) {
        int b = idx >> 6, h = idx & 63;
        float s = __ldg(b2 + h);
        for (int j = 0; j < 128; j++) s = fmaf(a1[b * 128 + j], __ldg(W2 + j * 64 + h), s);
        a2[idx] = s;
    }
    __syncthreads();
    if (t < 64) {
        float m = 0.f;
#pragma unroll
        for (int b = 0; b < Bc; b++) m += a2[b * 64 + t];
        m *= 0.125f;
        float v = 0.f;
#pragma unroll
        for (int b = 0; b < Bc; b++) { float dd = a2[b * 64 + t] - m; v = fmaf(dd, dd, v); }
        v *= 0.125f;
        float sc = rsqrtf(v + EPSc) * __ldg(g2 + t);
        float sh = __ldg(be2 + t);
#pragma unroll
        for (int b = 0; b < Bc; b++) {
            float z = (a2[b * 64 + t] - m) * sc + sh;
            a2[b * 64 + t] = z > 0.f ? z : 0.f;
        }
    }
    __syncthreads();
    for (int idx = t; idx < 512; idx += 256) {
        int b = idx >> 6, h = idx & 63;
        float s = __ldg(b3 + h);
        for (int j = 0; j < 64; j++) s = fmaf(a2[b * 64 + j], __ldg(W3 + j * 64 + h), s);
        a3[idx] = s;
    }
    __syncthreads();
    if (t < 64) {
        float m = 0.f;
#pragma unroll
        for (int b = 0; b < Bc; b++) m += a3[b * 64 + t];
        m *= 0.125f;
        float v = 0.f;
#pragma unroll
        for (int b = 0; b < Bc; b++) { float dd = a3[b * 64 + t] - m; v = fmaf(dd, dd, v); }
        v *= 0.125f;
        float sc = rsqrtf(v + EPSc) * __ldg(g3 + t);
        float sh = __ldg(be3 + t);
#pragma unroll
        for (int b = 0; b < Bc; b++) {
            float z = (a3[b * 64 + t] - m) * sc + sh;
            a3[b * 64 + t] = z > 0.f ? z : 0.f;
        }
    }
    __syncthreads();
    if (t < 16) {
        int b = t >> 1, c = t & 1;
        float s = __ldg(b4 + c);
        for (int j = 0; j < 64; j++) s = fmaf(a3[b * 64 + j], __ldg(W4 + j * 2 + c), s);
        lg[t] = s;
    }
    __syncthreads();
    if (t < 8) {
        float l0 = lg[t * 2], l1 = lg[t * 2 + 1];
        float m = fmaxf(l0, l1);
        float lse = m + logf(expf(l0 - m) + expf(l1 - m));
        out[t * 2 + 0] = l0 - lse;
        out[t * 2 + 1] = l1 - lse;
    }
}

// ---------------- host driver ----------------
extern "C" void kernel_launch(void* const* d_in, const int* in_sizes, int n_in,
                              void* d_out, int out_size) {
    const float* x    = (const float*)d_in[0];
    const int*   ei   = (const int*)d_in[1];
    int E = in_sizes[1] / 2;
    const int* src = ei;
    const int* dst = ei + E;
    const float* cw0  = (const float*)d_in[3];
    const float* cb0  = (const float*)d_in[4];
    const float* cw1  = (const float*)d_in[5];
    const float* cb1  = (const float*)d_in[6];
    const float* cw2  = (const float*)d_in[7];
    const float* cb2  = (const float*)d_in[8];
    const float* bnhg = (const float*)d_in[9];
    const float* bnhb = (const float*)d_in[10];
    const float* bng  = (const float*)d_in[11];
    const float* bnb  = (const float*)d_in[12];
    const float* w1   = (const float*)d_in[13];
    const float* b1   = (const float*)d_in[14];
    const float* g1   = (const float*)d_in[15];
    const float* be1  = (const float*)d_in[16];
    const float* W2   = (const float*)d_in[17];
    const float* b2   = (const float*)d_in[18];
    const float* g2   = (const float*)d_in[19];
    const float* be2  = (const float*)d_in[20];
    const float* W3   = (const float*)d_in[21];
    const float* b3   = (const float*)d_in[22];
    const float* g3   = (const float*)d_in[23];
    const float* be3  = (const float*)d_in[24];
    const float* W4   = (const float*)d_in[25];
    const float* b4   = (const float*)d_in[26];
    float* out = (float*)d_out;

    void* y1ptr = nullptr;
    void* curptr = nullptr;
    cudaGetSymbolAddress(&y1ptr, g_y1);
    cudaGetSymbolAddress(&curptr, g_cursor);

    cudaStream_t s2 = 0;
    cudaEvent_t evF = 0, evJ = 0;
    bool forked = (cudaStreamCreateWithFlags(&s2, cudaStreamNonBlocking) == cudaSuccess) &&
                  (cudaEventCreateWithFlags(&evF, cudaEventDisableTiming) == cudaSuccess) &&
                  (cudaEventCreateWithFlags(&evJ, cudaEventDisableTiming) == cudaSuccess);
    if (!forked) s2 = 0;

    if (forked) {
        cudaEventRecord(evF, 0);
        cudaStreamWaitEvent(s2, evF, 0);
    }

    // cheb first (64 big-smem blocks grab their SMs immediately)
    cudaFuncSetAttribute(cheb_kernel, cudaFuncAttributeMaxDynamicSharedMemorySize,
                         SM_TOT * (int)sizeof(float));
    cheb_kernel<<<64, 1024, SM_TOT * sizeof(float)>>>(src, dst, E,
                                                      cw0, cb0, cw1, cb1, cw2, cb2);

    cudaMemsetAsync(y1ptr, 0, Bc * HIDc * sizeof(float), s2);
    cudaMemsetAsync(curptr, 0, sizeof(int), s2);
    gemm_kernel<<<GNB, 256, 0, s2>>>(x, w1, bng, bnb);
    if (forked) cudaEventRecord(evJ, s2);

    if (forked) cudaStreamWaitEvent(0, evJ, 0);
    head_kernel<<<1, 256>>>(bnhg, bnhb, b1, g1, be1, W2, b2, g2, be2,
                            W3, b3, g3, be3, W4, b4, out);
}